// round 8
// baseline (speedup 1.0000x reference)
#include <cuda_runtime.h>
#include <cuda_fp16.h>
#include <math.h>
#include <cstdint>

#define D      256
#define R      16
#define N0     8192
#define L      6
#define NL     8192
#define TOTAL  (N0 + L * NL)   // 57344
#define EVAL_BLOCKS 224

#define K1 512
#define K2 256

// ---------------- scratch (device globals; no allocation) ----------------
__device__ float  g_store[(size_t)TOTAL * D];     // fp32 embeddings (eval)
__device__ __half g_storeh[(size_t)TOTAL * D];    // fp16 k-interleaved mirror
__device__ __half g_Hh[(size_t)NL * D];           // hidden, fp16 interleaved
__device__ __half g_W1h[(size_t)R * D * K1];      // stage-contiguous fp16 W1^T
__device__ __half g_W2h[(size_t)R * D * K2];
__device__ float  g_partials[EVAL_BLOCKS * 5];

__device__ __forceinline__ uint32_t smem_to_u32(const void* p) {
    uint32_t a;
    asm("{ .reg .u64 t; cvta.to.shared.u64 t, %1; cvt.u32.u64 %0, t; }" : "=r"(a) : "l"(p));
    return a;
}

// interleave position of k within a 32-k group: thread t4's fragment halves
// {2t4,2t4+1,2t4+8,2t4+9} x two k16-steps are 16B contiguous.
__device__ __forceinline__ int pos32(int k5) {
    return ((k5 >> 1) & 3) * 8 + (k5 >> 4) * 4 + ((k5 >> 3) & 1) * 2 + (k5 & 1);
}

#define MBARRIER_INIT(mbar, cnt) \
    asm volatile("mbarrier.init.shared.b64 [%0], %1;" \
                 :: "r"((uint32_t)(mbar)), "r"((uint32_t)(cnt)) : "memory")
#define MBARRIER_EXPECT_TX(mbar, bytes) \
    asm volatile("mbarrier.arrive.expect_tx.shared.b64 _, [%0], %1;" \
                 :: "r"((uint32_t)(mbar)), "r"((uint32_t)(bytes)) : "memory")
#define MBARRIER_WAIT_PARITY(mbar_a, par) do { \
    uint32_t _m = (uint32_t)(mbar_a), _p = (uint32_t)(par), _d; \
    asm volatile("{\n\t.reg .pred p;\n\t" \
        "mbarrier.try_wait.parity.acquire.cta.shared::cta.b64 p, [%1], %2;\n\t" \
        "selp.b32 %0, 1, 0, p;\n\t}" : "=r"(_d) : "r"(_m), "r"(_p) : "memory"); \
    if (!_d) { \
        asm volatile("{\n\t.reg .pred P1;\n\t" \
            "WL_%=:\n\t" \
            "mbarrier.try_wait.parity.acquire.cta.shared::cta.b64 P1, [%0], %1, 0x989680;\n\t" \
            "@P1 bra.uni WD_%=;\n\t" \
            "bra.uni WL_%=;\n\t" \
            "WD_%=:\n\t}" :: "r"(_m), "r"(_p) : "memory"); \
    } \
} while (0)
#define BULK_G2S(dst_u32, src_ptr, bytes, mbar_u32) \
    asm volatile("cp.async.bulk.shared::cta.global.mbarrier::complete_tx::bytes " \
                 "[%0], [%1], %2, [%3];" \
                 :: "r"(dst_u32), "l"(src_ptr), "r"((uint32_t)(bytes)), \
                    "r"(mbar_u32) : "memory")

// ---------------- init: fp32 + interleaved fp16 ----------------
__global__ void init_gather(const int* __restrict__ thax,
                            const float* __restrict__ table) {
    int t = blockIdx.x * blockDim.x + threadIdx.x;
    int row = t >> 6, c = t & 63;
    if (row < N0) {
        int tid_ = thax[row];
        float4 v = ((const float4*)(table + (size_t)tid_ * D))[c];
        ((float4*)g_store)[(size_t)row * 64 + c] = v;
        int k = c * 4;
        __half* hdst = g_storeh + (size_t)row * D + (k >> 5) * 32;
        int k5 = k & 31;
        *(__half2*)(hdst + pos32(k5))     = __floats2half2_rn(v.x, v.y);
        *(__half2*)(hdst + pos32(k5 + 2)) = __floats2half2_rn(v.z, v.w);
    }
}

// ---------------- weight convert ----------------
// W[R][K][256] -> Wt stage-contiguous: [R][h(2)][s(K/32)][n(128)][k(32 interleaved)]
template<int K, bool FIRST>
__global__ void convert_w(const float* __restrict__ W) {
    int s = blockIdx.x, r = blockIdx.y, c = threadIdx.x;   // c: h*128+n
    int h = c >> 7, n = c & 127;
    const float* Wr = W + ((size_t)r * K + s * 32) * D + h * 128 + n;
    __half loc[32];
#pragma unroll
    for (int k5 = 0; k5 < 32; k5++)
        loc[pos32(k5)] = __float2half_rn(Wr[(size_t)k5 * D]);
    __half* dst = (FIRST ? g_W1h : g_W2h)
                + ((size_t)((r * 2 + h) * (K / 32) + s) * 128 + n) * 32;
    uint4* d4 = (uint4*)dst;
    const uint4* s4 = (const uint4*)loc;
#pragma unroll
    for (int i = 0; i < 4; i++) d4[i] = s4[i];
}

// ---------------- fp16 GEMM, bulk-DMA fed ----------------
// FIRST: g_Hh[m, n0:+128] = relu(gather(par)[64xK1] @ W1[r] + b1)
// else : g_store/g_storeh[...] = g_Hh @ W2[r] + b2
// CTA 128 thr (4 warps 2x2), BM=64, BN=128, warp 32x64, mma m16n8k16.
// A: fully smem-resident (64 x AS halfs, AS = K+32 -> conflict-free LDS).
// B: 4-stage ring of 8KB bulk copies.
template<int K, bool FIRST>
__global__ void __launch_bounds__(128)
gemm_h(const float* __restrict__ bias, const int* __restrict__ par, int layer) {
    constexpr int NIT = K / 32;
    constexpr int AS  = K + 32;          // halfs; 2*AS % 128 == 64 -> conflict-free
    extern __shared__ __half sm[];       // A: 64*AS, then B: 4*4096
    __shared__ __align__(8) uint64_t mbars[5];   // [0]=A, [1..4]=B stages
    const uint32_t mbarA = smem_to_u32(&mbars[0]);
    const uint32_t smA   = smem_to_u32(sm);
    __half* smB = sm + 64 * AS;
    const uint32_t smBu = smem_to_u32(smB);

    const int tid  = threadIdx.x;
    const int lane = tid & 31;
    const int wid  = tid >> 5;
    const int g    = lane >> 2, t4 = lane & 3;
    const int warp_m = wid >> 1, warp_n = wid & 1;
    const int m0 = blockIdx.x * 64;
    const int n0 = blockIdx.y * 128;
    const int r  = m0 >> 9;

    const __half* Wh = (FIRST ? g_W1h : g_W2h)
                     + (size_t)((r * 2 + blockIdx.y) * NIT) * 4096;

    // ---- barriers init ----
    if (tid == 0) {
#pragma unroll
        for (int i = 0; i < 5; i++) MBARRIER_INIT(smem_to_u32(&mbars[i]), 1);
        asm volatile("fence.proxy.async.shared::cta;" ::: "memory");
    }
    __syncthreads();

    // ---- issue A (whole tile) + first 3 B stages ----
    if (tid == 0) MBARRIER_EXPECT_TX(mbarA, FIRST ? 64 * 1024 : 32 * 1024);
    __syncthreads();
    if (FIRST) {
        if (tid < 128) {
            int row = tid >> 1, p = tid & 1;
            const __half* src = g_storeh + (size_t)par[2 * (m0 + row) + p] * D;
            uint32_t dst = smA + (uint32_t)(row * AS + p * 256) * 2u;
            BULK_G2S(dst, src, 512, mbarA);
        }
    } else {
        if (tid < 64) {
            const __half* src = g_Hh + (size_t)(m0 + tid) * D;
            uint32_t dst = smA + (uint32_t)(tid * AS) * 2u;
            BULK_G2S(dst, src, 512, mbarA);
        }
    }
    if (tid == 0) {
#pragma unroll
        for (int s = 0; s < 3; s++) {
            uint32_t mb = smem_to_u32(&mbars[1 + s]);
            MBARRIER_EXPECT_TX(mb, 8192);
            BULK_G2S(smBu + (uint32_t)(s * 4096) * 2u, Wh + (size_t)s * 4096, 8192, mb);
        }
    }

    float acc[2][8][4];
#pragma unroll
    for (int mt = 0; mt < 2; mt++)
#pragma unroll
        for (int nt = 0; nt < 8; nt++)
#pragma unroll
            for (int c = 0; c < 4; c++) acc[mt][nt][c] = 0.f;

    for (int it = 0; it < NIT; it++) {
        __syncthreads();              // all warps done with buffer (it+3)&3
        if (tid == 0 && it + 3 < NIT) {
            int s = it + 3;
            uint32_t mb = smem_to_u32(&mbars[1 + (s & 3)]);
            MBARRIER_EXPECT_TX(mb, 8192);
            BULK_G2S(smBu + (uint32_t)((s & 3) * 4096) * 2u,
                     Wh + (size_t)s * 4096, 8192, mb);
        }
        if (it == 0) MBARRIER_WAIT_PARITY(mbarA, 0);
        MBARRIER_WAIT_PARITY(smem_to_u32(&mbars[1 + (it & 3)]), (it >> 2) & 1);

        const __half* As = sm + it * 32;
        const __half* Bs = smB + (it & 3) * 4096;

        uint4 Av[2][2];
#pragma unroll
        for (int mt = 0; mt < 2; mt++) {
            int r0 = warp_m * 32 + mt * 16 + g;
            Av[mt][0] = *(const uint4*)(As + r0 * AS + t4 * 8);
            Av[mt][1] = *(const uint4*)(As + (r0 + 8) * AS + t4 * 8);
        }
        uint4 Bv[8];
#pragma unroll
        for (int nt = 0; nt < 8; nt++) {
            int cc = warp_n * 64 + nt * 8 + g;
            Bv[nt] = *(const uint4*)(Bs + cc * 32 + t4 * 8);
        }
#pragma unroll
        for (int step = 0; step < 2; step++) {
#pragma unroll
            for (int mt = 0; mt < 2; mt++) {
                uint32_t a0 = step ? Av[mt][0].z : Av[mt][0].x;
                uint32_t a1 = step ? Av[mt][1].z : Av[mt][1].x;
                uint32_t a2 = step ? Av[mt][0].w : Av[mt][0].y;
                uint32_t a3 = step ? Av[mt][1].w : Av[mt][1].y;
#pragma unroll
                for (int nt = 0; nt < 8; nt++) {
                    uint32_t b0 = step ? Bv[nt].z : Bv[nt].x;
                    uint32_t b1 = step ? Bv[nt].w : Bv[nt].y;
                    asm volatile(
                        "mma.sync.aligned.m16n8k16.row.col.f32.f16.f16.f32 "
                        "{%0,%1,%2,%3}, {%4,%5,%6,%7}, {%8,%9}, {%0,%1,%2,%3};"
                        : "+f"(acc[mt][nt][0]), "+f"(acc[mt][nt][1]),
                          "+f"(acc[mt][nt][2]), "+f"(acc[mt][nt][3])
                        : "r"(a0), "r"(a1), "r"(a2), "r"(a3), "r"(b0), "r"(b1));
                }
            }
        }
    }

    // ---- epilogue ----
    const float* br = bias + r * D + n0;
#pragma unroll
    for (int mt = 0; mt < 2; mt++) {
        int mr0 = m0 + warp_m * 32 + mt * 16 + g;
#pragma unroll
        for (int nt = 0; nt < 8; nt++) {
            int lcol = warp_n * 64 + nt * 8 + 2 * t4;
            int col  = n0 + lcol;
            float bx = br[lcol], by = br[lcol + 1];
            float x0 = acc[mt][nt][0] + bx, y0 = acc[mt][nt][1] + by;
            float x1 = acc[mt][nt][2] + bx, y1 = acc[mt][nt][3] + by;
            int hoff = (col >> 5) * 32 + pos32(col & 31);
            if (FIRST) {
                x0 = fmaxf(x0, 0.f); y0 = fmaxf(y0, 0.f);
                x1 = fmaxf(x1, 0.f); y1 = fmaxf(y1, 0.f);
                *(__half2*)(g_Hh + (size_t)mr0 * D + hoff)       = __floats2half2_rn(x0, y0);
                *(__half2*)(g_Hh + (size_t)(mr0 + 8) * D + hoff) = __floats2half2_rn(x1, y1);
            } else {
                float*  C  = g_store  + (size_t)(N0 + layer * NL) * D;
                __half* Ch = g_storeh + (size_t)(N0 + layer * NL) * D;
                float2 v0 = {x0, y0}, v1 = {x1, y1};
                *(float2*)(C + (size_t)mr0 * D + col)        = v0;
                *(float2*)(C + (size_t)(mr0 + 8) * D + col)  = v1;
                *(__half2*)(Ch + (size_t)mr0 * D + hoff)       = __floats2half2_rn(x0, y0);
                *(__half2*)(Ch + (size_t)(mr0 + 8) * D + hoff) = __floats2half2_rn(x1, y1);
            }
        }
    }
}

// ---------------- eval + loss (deterministic two-stage reduction) ----------------
__device__ __forceinline__ float softplusf(float x) {
    return fmaxf(x, 0.f) + log1pf(expf(-fabsf(x)));
}

__global__ void __launch_bounds__(256)
eval_partial(const float* __restrict__ pos_vals, const float* __restrict__ neg_vals,
             const float* __restrict__ eval_w, const float* __restrict__ eval_b,
             const float* __restrict__ pos_weight) {
    __shared__ float red[8][5];
    const int lane = threadIdx.x & 31, warp = threadIdx.x >> 5;
    const int gw = blockIdx.x * 8 + warp;

    float w[8];
#pragma unroll
    for (int j = 0; j < 8; j++) w[j] = eval_w[lane + 32 * j];
    const float eb = *eval_b;
    const float pw = *pos_weight;

    float loss = 0.f, posOK = 0.f, negOK = 0.f, posTot = 0.f, negTot = 0.f;

    for (int node = gw; node < TOTAL; node += EVAL_BLOCKS * 8) {
        const float* row = g_store + (size_t)node * D;
        float s = 0.f;
#pragma unroll
        for (int j = 0; j < 8; j++) s += row[lane + 32 * j] * w[j];
#pragma unroll
        for (int off = 16; off; off >>= 1) s += __shfl_xor_sync(0xffffffffu, s, off);
        if (lane == 0) {
            float x = s + eb;
            float pv = pos_vals[node], nv = neg_vals[node];
            float tot = pv + nv;
            if (tot > 0.f) {
                float tgt = pv / fmaxf(tot, 1e-9f);
                float bce = pw * tgt * softplusf(-x) + (1.f - tgt) * softplusf(x);
                loss += tot * bce;
                posTot += pv; negTot += nv;
                if (x >= 0.f) posOK += pv; else negOK += nv;
            }
        }
    }
    if (lane == 0) {
        red[warp][0] = loss; red[warp][1] = posOK; red[warp][2] = negOK;
        red[warp][3] = posTot; red[warp][4] = negTot;
    }
    __syncthreads();
    if (threadIdx.x < 5) {
        float t = 0.f;
        for (int i = 0; i < 8; i++) t += red[i][threadIdx.x];
        g_partials[blockIdx.x * 5 + threadIdx.x] = t;
    }
}

__global__ void final_reduce(float* __restrict__ out, int out_size) {
    float s[5] = {0.f, 0.f, 0.f, 0.f, 0.f};
    for (int i = threadIdx.x; i < EVAL_BLOCKS; i += 32)
#pragma unroll
        for (int c = 0; c < 5; c++) s[c] += g_partials[i * 5 + c];
#pragma unroll
    for (int c = 0; c < 5; c++)
#pragma unroll
        for (int off = 16; off; off >>= 1)
            s[c] += __shfl_xor_sync(0xffffffffu, s[c], off);
    if (threadIdx.x == 0) {
        float loss = s[0], posOK = s[1], negOK = s[2], posTot = s[3], negTot = s[4];
        float pos_rate = (posTot > 0.f) ? posOK / fmaxf(posTot, 1e-9f) : 1.f;
        float neg_rate = (negTot > 0.f) ? negOK / fmaxf(negTot, 1e-9f) : 1.f;
        if (out_size >= 1) out[0] = loss;
        if (out_size >= 2) out[1] = pos_rate;
        if (out_size >= 3) out[2] = neg_rate;
    }
}

// ---------------- launch ----------------
extern "C" void kernel_launch(void* const* d_in, const int* in_sizes, int n_in,
                              void* d_out, int out_size) {
    const int*   thax       = (const int*)  d_in[0];
    const int*   par_idx    = (const int*)  d_in[1];
    const float* pos_vals   = (const float*)d_in[2];
    const float* neg_vals   = (const float*)d_in[3];
    const float* init_table = (const float*)d_in[4];
    const float* W1         = (const float*)d_in[5];
    const float* b1         = (const float*)d_in[6];
    const float* W2         = (const float*)d_in[7];
    const float* b2         = (const float*)d_in[8];
    const float* eval_w     = (const float*)d_in[9];
    const float* eval_b     = (const float*)d_in[10];
    const float* pos_weight = (const float*)d_in[11];
    float* out = (float*)d_out;

    constexpr int SM1 = (64 * (K1 + 32) + 4 * 4096) * 2;   // 102400
    constexpr int SM2 = (64 * (K2 + 32) + 4 * 4096) * 2;   // 69632
    cudaFuncSetAttribute(gemm_h<K1, true>,
                         cudaFuncAttributeMaxDynamicSharedMemorySize, SM1);
    cudaFuncSetAttribute(gemm_h<K2, false>,
                         cudaFuncAttributeMaxDynamicSharedMemorySize, SM2);

    init_gather<<<(N0 * 64) / 256, 256>>>(thax, init_table);
    convert_w<K1, true ><<<dim3(K1 / 32, R), 256>>>(W1);
    convert_w<K2, false><<<dim3(K2 / 32, R), 256>>>(W2);

    for (int l = 0; l < L; l++) {
        gemm_h<K1, true ><<<dim3(NL / 64, 2), 128, SM1>>>(
            b1, par_idx + (size_t)l * NL * 2, l);
        gemm_h<K2, false><<<dim3(NL / 64, 2), 128, SM2>>>(
            b2, nullptr, l);
    }

    eval_partial<<<EVAL_BLOCKS, 256>>>(pos_vals, neg_vals, eval_w, eval_b, pos_weight);
    final_reduce<<<1, 32>>>(out, out_size);
}

// round 9
// speedup vs baseline: 1.1919x; 1.1919x over previous
#include <cuda_runtime.h>
#include <cuda_fp16.h>
#include <math.h>
#include <cstdint>

#define D      256
#define R      16
#define N0     8192
#define L      6
#define NL     8192
#define TOTAL  (N0 + L * NL)   // 57344
#define EVAL_BLOCKS 224

#define K1 512
#define K2 256

// ---------------- scratch (device globals; no allocation) ----------------
__device__ __half g_storeh[(size_t)TOTAL * D];    // fp16 k-interleaved embeddings
__device__ __half g_Hh[(size_t)NL * D];           // hidden, fp16 interleaved
__device__ __half g_W1h[(size_t)R * D * K1];      // stage-contiguous fp16 W1^T
__device__ __half g_W2h[(size_t)R * D * K2];
__device__ float  g_partials[EVAL_BLOCKS * 5];

__device__ __forceinline__ uint32_t smem_to_u32(const void* p) {
    uint32_t a;
    asm("{ .reg .u64 t; cvta.to.shared.u64 t, %1; cvt.u32.u64 %0, t; }" : "=r"(a) : "l"(p));
    return a;
}

// interleave position of k within a 32-k group: thread t4's fragment halves
// {2t4,2t4+1,2t4+8,2t4+9} x two k16-steps are 16B contiguous.
__device__ __forceinline__ int pos32(int k5) {
    return ((k5 >> 1) & 3) * 8 + (k5 >> 4) * 4 + ((k5 >> 3) & 1) * 2 + (k5 & 1);
}
// inverse: k for storage position p (within a 32 group)
__device__ __forceinline__ int invpos32(int p) {
    return (((p >> 2) & 1) << 4) | (((p >> 1) & 1) << 3) | (((p >> 3) & 3) << 1) | (p & 1);
}

#define MBARRIER_INIT(mbar, cnt) \
    asm volatile("mbarrier.init.shared.b64 [%0], %1;" \
                 :: "r"((uint32_t)(mbar)), "r"((uint32_t)(cnt)) : "memory")
#define MBARRIER_EXPECT_TX(mbar, bytes) \
    asm volatile("mbarrier.arrive.expect_tx.shared.b64 _, [%0], %1;" \
                 :: "r"((uint32_t)(mbar)), "r"((uint32_t)(bytes)) : "memory")
#define MBARRIER_WAIT_PARITY(mbar_a, par) do { \
    uint32_t _m = (uint32_t)(mbar_a), _p = (uint32_t)(par), _d; \
    asm volatile("{\n\t.reg .pred p;\n\t" \
        "mbarrier.try_wait.parity.acquire.cta.shared::cta.b64 p, [%1], %2;\n\t" \
        "selp.b32 %0, 1, 0, p;\n\t}" : "=r"(_d) : "r"(_m), "r"(_p) : "memory"); \
    if (!_d) { \
        asm volatile("{\n\t.reg .pred P1;\n\t" \
            "WL_%=:\n\t" \
            "mbarrier.try_wait.parity.acquire.cta.shared::cta.b64 P1, [%0], %1, 0x989680;\n\t" \
            "@P1 bra.uni WD_%=;\n\t" \
            "bra.uni WL_%=;\n\t" \
            "WD_%=:\n\t}" :: "r"(_m), "r"(_p) : "memory"); \
    } \
} while (0)
#define BULK_G2S(dst_u32, src_ptr, bytes, mbar_u32) \
    asm volatile("cp.async.bulk.shared::cta.global.mbarrier::complete_tx::bytes " \
                 "[%0], [%1], %2, [%3];" \
                 :: "r"(dst_u32), "l"(src_ptr), "r"((uint32_t)(bytes)), \
                    "r"(mbar_u32) : "memory")

// ---------------- init: interleaved fp16 store ----------------
__global__ void init_gather(const int* __restrict__ thax,
                            const float* __restrict__ table) {
    int t = blockIdx.x * blockDim.x + threadIdx.x;
    int row = t >> 6, c = t & 63;
    if (row < N0) {
        int tid_ = thax[row];
        float4 v = ((const float4*)(table + (size_t)tid_ * D))[c];
        int k = c * 4;
        __half* hdst = g_storeh + (size_t)row * D + (k >> 5) * 32;
        int k5 = k & 31;
        *(__half2*)(hdst + pos32(k5))     = __floats2half2_rn(v.x, v.y);
        *(__half2*)(hdst + pos32(k5 + 2)) = __floats2half2_rn(v.z, v.w);
    }
}

// ---------------- weight convert ----------------
// W[R][K][256] -> Wt stage-contiguous: [R][h(2)][s(K/32)][n(128)][k(32 interleaved)]
template<int K, bool FIRST>
__global__ void convert_w(const float* __restrict__ W) {
    int s = blockIdx.x, r = blockIdx.y, c = threadIdx.x;
    int h = c >> 7, n = c & 127;
    const float* Wr = W + ((size_t)r * K + s * 32) * D + h * 128 + n;
    __half loc[32];
#pragma unroll
    for (int k5 = 0; k5 < 32; k5++)
        loc[pos32(k5)] = __float2half_rn(Wr[(size_t)k5 * D]);
    __half* dst = (FIRST ? g_W1h : g_W2h)
                + ((size_t)((r * 2 + h) * (K / 32) + s) * 128 + n) * 32;
    uint4* d4 = (uint4*)dst;
    const uint4* s4 = (const uint4*)loc;
#pragma unroll
    for (int i = 0; i < 4; i++) d4[i] = s4[i];
}

// ---------------- fp16 GEMM: 256 thr, 8 warps (2m x 4n), warp tile 32x32 ----------------
// FIRST: g_Hh[m, n0:+128] = relu(gather(par)[64xK1] @ W1[r] + b1)
// else : g_storeh[...] = g_Hh @ W2[r] + b2
// BM=64, BN=128, BK=32, 4 stages. A: cp.async (1 x 16B/thread/stage).
// B: bulk DMA 8KB/stage. smem 48KB dynamic -> 2 CTA/SM.
template<int K, bool FIRST>
__global__ void __launch_bounds__(256)
gemm_h(const float* __restrict__ bias, const int* __restrict__ par, int layer) {
    constexpr int NIT = K / 32;
    extern __shared__ __half sm[];       // A: 4 x 2048, B: 4 x 4096 (49152 B)
    __shared__ __align__(8) uint64_t mbars[4];
    const uint32_t smA  = smem_to_u32(sm);
    __half* smB = sm + 8192;
    const uint32_t smBu = smem_to_u32(smB);

    const int tid  = threadIdx.x;
    const int lane = tid & 31;
    const int wid  = tid >> 5;
    const int g    = lane >> 2, t4 = lane & 3;
    const int warp_m = wid >> 2, warp_n = wid & 3;
    const int m0 = blockIdx.x * 64;
    const int n0 = blockIdx.y * 128;
    const int r  = m0 >> 9;

    // A loader: row = tid>>2 (0..63), chunk = tid&3 (16B of the 64B stage-row)
    const int arow = tid >> 2, achk = tid & 3;
    const __half* aP0;
    const __half* aP1 = nullptr;
    if (FIRST) {
        aP0 = g_storeh + (size_t)par[2 * (m0 + arow)] * D;
        aP1 = g_storeh + (size_t)par[2 * (m0 + arow) + 1] * D;
    } else {
        aP0 = g_Hh + (size_t)(m0 + arow) * D;
    }
    const __half* Wh = (FIRST ? g_W1h : g_W2h)
                     + (size_t)((r * 2 + blockIdx.y) * NIT) * 4096;

    auto issueA = [&](int s) {
        const __half* src;
        if (FIRST) src = ((s < 8) ? (aP0 + s * 32) : (aP1 + (s - 8) * 32)) + achk * 8;
        else       src = aP0 + s * 32 + achk * 8;
        uint32_t dst = smA + (uint32_t)((s & 3) * 2048 + arow * 32 + achk * 8) * 2u;
        asm volatile("cp.async.cg.shared.global [%0], [%1], 16;" :: "r"(dst), "l"(src));
    };
    auto issueB = [&](int s) {   // call from tid==0 only
        uint32_t mb = smem_to_u32(&mbars[s & 3]);
        MBARRIER_EXPECT_TX(mb, 8192);
        BULK_G2S(smBu + (uint32_t)((s & 3) * 4096) * 2u, Wh + (size_t)s * 4096, 8192, mb);
    };

    if (tid == 0) {
#pragma unroll
        for (int i = 0; i < 4; i++) MBARRIER_INIT(smem_to_u32(&mbars[i]), 1);
        asm volatile("fence.proxy.async.shared::cta;" ::: "memory");
    }
    __syncthreads();

    issueA(0); asm volatile("cp.async.commit_group;");
    issueA(1); asm volatile("cp.async.commit_group;");
    issueA(2); asm volatile("cp.async.commit_group;");
    if (tid == 0) { issueB(0); issueB(1); issueB(2); }

    float acc[2][4][4];
#pragma unroll
    for (int mt = 0; mt < 2; mt++)
#pragma unroll
        for (int nt = 0; nt < 4; nt++)
#pragma unroll
            for (int c = 0; c < 4; c++) acc[mt][nt][c] = 0.f;

    for (int it = 0; it < NIT; it++) {
        int rem = NIT - 1 - it;
        if (rem >= 2)      asm volatile("cp.async.wait_group 2;");
        else if (rem == 1) asm volatile("cp.async.wait_group 1;");
        else               asm volatile("cp.async.wait_group 0;");
        MBARRIER_WAIT_PARITY(smem_to_u32(&mbars[it & 3]), (it >> 2) & 1);
        __syncthreads();                       // stage it visible; buffer (it-1)&3 free
        if (it + 3 < NIT) {
            issueA(it + 3); asm volatile("cp.async.commit_group;");
            if (tid == 0) issueB(it + 3);
        }

        const __half* As = sm + (it & 3) * 2048;
        const __half* Bs = smB + (it & 3) * 4096;

        uint4 Av[2][2];
#pragma unroll
        for (int mt = 0; mt < 2; mt++) {
            int r0 = warp_m * 32 + mt * 16 + g;
            Av[mt][0] = *(const uint4*)(As + r0 * 32 + t4 * 8);
            Av[mt][1] = *(const uint4*)(As + (r0 + 8) * 32 + t4 * 8);
        }
        uint4 Bv[4];
#pragma unroll
        for (int nt = 0; nt < 4; nt++) {
            int cc = warp_n * 32 + nt * 8 + g;
            Bv[nt] = *(const uint4*)(Bs + cc * 32 + t4 * 8);
        }
#pragma unroll
        for (int step = 0; step < 2; step++) {
#pragma unroll
            for (int mt = 0; mt < 2; mt++) {
                uint32_t a0 = step ? Av[mt][0].z : Av[mt][0].x;
                uint32_t a1 = step ? Av[mt][1].z : Av[mt][1].x;
                uint32_t a2 = step ? Av[mt][0].w : Av[mt][0].y;
                uint32_t a3 = step ? Av[mt][1].w : Av[mt][1].y;
#pragma unroll
                for (int nt = 0; nt < 4; nt++) {
                    uint32_t b0 = step ? Bv[nt].z : Bv[nt].x;
                    uint32_t b1 = step ? Bv[nt].w : Bv[nt].y;
                    asm volatile(
                        "mma.sync.aligned.m16n8k16.row.col.f32.f16.f16.f32 "
                        "{%0,%1,%2,%3}, {%4,%5,%6,%7}, {%8,%9}, {%0,%1,%2,%3};"
                        : "+f"(acc[mt][nt][0]), "+f"(acc[mt][nt][1]),
                          "+f"(acc[mt][nt][2]), "+f"(acc[mt][nt][3])
                        : "r"(a0), "r"(a1), "r"(a2), "r"(a3), "r"(b0), "r"(b1));
                }
            }
        }
    }

    // ---- epilogue: bias (+relu), fp16 interleaved store ----
    __half* Cbase = FIRST ? g_Hh : (g_storeh + (size_t)(N0 + layer * NL) * D);
    const float* br = bias + r * D + n0;
#pragma unroll
    for (int mt = 0; mt < 2; mt++) {
        int mr0 = m0 + warp_m * 32 + mt * 16 + g;
#pragma unroll
        for (int nt = 0; nt < 4; nt++) {
            int lcol = warp_n * 32 + nt * 8 + 2 * t4;
            int col  = n0 + lcol;
            float bx = br[lcol], by = br[lcol + 1];
            float x0 = acc[mt][nt][0] + bx, y0 = acc[mt][nt][1] + by;
            float x1 = acc[mt][nt][2] + bx, y1 = acc[mt][nt][3] + by;
            if (FIRST) {
                x0 = fmaxf(x0, 0.f); y0 = fmaxf(y0, 0.f);
                x1 = fmaxf(x1, 0.f); y1 = fmaxf(y1, 0.f);
            }
            int hoff = (col >> 5) * 32 + pos32(col & 31);   // even col -> aligned half2
            *(__half2*)(Cbase + (size_t)mr0 * D + hoff)       = __floats2half2_rn(x0, y0);
            *(__half2*)(Cbase + (size_t)(mr0 + 8) * D + hoff) = __floats2half2_rn(x1, y1);
        }
    }
}

// ---------------- eval + loss from fp16 interleaved store ----------------
__device__ __forceinline__ float softplusf(float x) {
    return fmaxf(x, 0.f) + log1pf(expf(-fabsf(x)));
}

__global__ void __launch_bounds__(256)
eval_partial(const float* __restrict__ pos_vals, const float* __restrict__ neg_vals,
             const float* __restrict__ eval_w, const float* __restrict__ eval_b,
             const float* __restrict__ pos_weight) {
    __shared__ float red[8][5];
    const int lane = threadIdx.x & 31, warp = threadIdx.x >> 5;
    const int gw = blockIdx.x * 8 + warp;

    // this lane covers storage positions [lane*8, lane*8+8); load w through inverse perm
    float w[8];
#pragma unroll
    for (int j = 0; j < 8; j++) {
        int q = lane * 8 + j;
        int k = (q >> 5) * 32 + invpos32(q & 31);
        w[j] = eval_w[k];
    }
    const float eb = *eval_b;
    const float pw = *pos_weight;

    float loss = 0.f, posOK = 0.f, negOK = 0.f, posTot = 0.f, negTot = 0.f;

    for (int node = gw; node < TOTAL; node += EVAL_BLOCKS * 8) {
        const __half2* row = (const __half2*)(g_storeh + (size_t)node * D);
        float s = 0.f;
#pragma unroll
        for (int i = 0; i < 4; i++) {
            float2 v = __half22float2(row[lane * 4 + i]);
            s += v.x * w[2 * i] + v.y * w[2 * i + 1];
        }
#pragma unroll
        for (int off = 16; off; off >>= 1) s += __shfl_xor_sync(0xffffffffu, s, off);
        if (lane == 0) {
            float x = s + eb;
            float pv = pos_vals[node], nv = neg_vals[node];
            float tot = pv + nv;
            if (tot > 0.f) {
                float tgt = pv / fmaxf(tot, 1e-9f);
                float bce = pw * tgt * softplusf(-x) + (1.f - tgt) * softplusf(x);
                loss += tot * bce;
                posTot += pv; negTot += nv;
                if (x >= 0.f) posOK += pv; else negOK += nv;
            }
        }
    }
    if (lane == 0) {
        red[warp][0] = loss; red[warp][1] = posOK; red[warp][2] = negOK;
        red[warp][3] = posTot; red[warp][4] = negTot;
    }
    __syncthreads();
    if (threadIdx.x < 5) {
        float t = 0.f;
        for (int i = 0; i < 8; i++) t += red[i][threadIdx.x];
        g_partials[blockIdx.x * 5 + threadIdx.x] = t;
    }
}

__global__ void final_reduce(float* __restrict__ out, int out_size) {
    float s[5] = {0.f, 0.f, 0.f, 0.f, 0.f};
    for (int i = threadIdx.x; i < EVAL_BLOCKS; i += 32)
#pragma unroll
        for (int c = 0; c < 5; c++) s[c] += g_partials[i * 5 + c];
#pragma unroll
    for (int c = 0; c < 5; c++)
#pragma unroll
        for (int off = 16; off; off >>= 1)
            s[c] += __shfl_xor_sync(0xffffffffu, s[c], off);
    if (threadIdx.x == 0) {
        float loss = s[0], posOK = s[1], negOK = s[2], posTot = s[3], negTot = s[4];
        float pos_rate = (posTot > 0.f) ? posOK / fmaxf(posTot, 1e-9f) : 1.f;
        float neg_rate = (negTot > 0.f) ? negOK / fmaxf(negTot, 1e-9f) : 1.f;
        if (out_size >= 1) out[0] = loss;
        if (out_size >= 2) out[1] = pos_rate;
        if (out_size >= 3) out[2] = neg_rate;
    }
}

// ---------------- launch ----------------
extern "C" void kernel_launch(void* const* d_in, const int* in_sizes, int n_in,
                              void* d_out, int out_size) {
    const int*   thax       = (const int*)  d_in[0];
    const int*   par_idx    = (const int*)  d_in[1];
    const float* pos_vals   = (const float*)d_in[2];
    const float* neg_vals   = (const float*)d_in[3];
    const float* init_table = (const float*)d_in[4];
    const float* W1         = (const float*)d_in[5];
    const float* b1         = (const float*)d_in[6];
    const float* W2         = (const float*)d_in[7];
    const float* b2         = (const float*)d_in[8];
    const float* eval_w     = (const float*)d_in[9];
    const float* eval_b     = (const float*)d_in[10];
    const float* pos_weight = (const float*)d_in[11];
    float* out = (float*)d_out;

    constexpr int SMEM = (4 * 2048 + 4 * 4096) * 2;   // 49152
    cudaFuncSetAttribute(gemm_h<K1, true>,
                         cudaFuncAttributeMaxDynamicSharedMemorySize, SMEM);
    cudaFuncSetAttribute(gemm_h<K2, false>,
                         cudaFuncAttributeMaxDynamicSharedMemorySize, SMEM);

    init_gather<<<(N0 * 64) / 256, 256>>>(thax, init_table);
    convert_w<K1, true ><<<dim3(K1 / 32, R), 256>>>(W1);
    convert_w<K2, false><<<dim3(K2 / 32, R), 256>>>(W2);

    for (int l = 0; l < L; l++) {
        gemm_h<K1, true ><<<dim3(NL / 64, 2), 256, SMEM>>>(
            b1, par_idx + (size_t)l * NL * 2, l);
        gemm_h<K2, false><<<dim3(NL / 64, 2), 256, SMEM>>>(
            b2, nullptr, l);
    }

    eval_partial<<<EVAL_BLOCKS, 256>>>(pos_vals, neg_vals, eval_w, eval_b, pos_weight);
    final_reduce<<<1, 32>>>(out, out_size);
}

// round 10
// speedup vs baseline: 1.3418x; 1.1258x over previous
#include <cuda_runtime.h>
#include <cuda_fp16.h>
#include <math.h>
#include <cstdint>

#define D      256
#define R      16
#define N0     8192
#define L      6
#define NL     8192
#define TOTAL  (N0 + L * NL)   // 57344
#define EVAL_BLOCKS 224

#define K1 512
#define K2 256
#define NIT1 16                // K1/32
#define NIT2 8                 // K2/32
#define NSTG (NIT1 + NIT2)     // 24 unified B stages

// smem layout (halfs)
#define AS     544             // A row stride (K1+32): conflict-free LDS.128 phases
#define HS     288             // H row stride: conflict-free
#define OFF_B  (64 * AS)                 // 34816
#define OFF_H  (OFF_B + 4 * 8192)        // + 4 stages x (256n x 32k)
#define SMEM_HALFS (OFF_H + 64 * HS)
#define SMEM_BYTES (SMEM_HALFS * 2)      // 172032

// ---------------- scratch (device globals; no allocation) ----------------
__device__ __half g_storeh[(size_t)TOTAL * D];    // fp16 k-interleaved embeddings
__device__ __half g_W1h[(size_t)R * D * K1];      // stage-contiguous fp16 W1^T
__device__ __half g_W2h[(size_t)R * D * K2];
__device__ float  g_partials[EVAL_BLOCKS * 5];

__device__ __forceinline__ uint32_t smem_to_u32(const void* p) {
    uint32_t a;
    asm("{ .reg .u64 t; cvta.to.shared.u64 t, %1; cvt.u32.u64 %0, t; }" : "=r"(a) : "l"(p));
    return a;
}

// interleave position of k within a 32-k group: thread t4's fragment halves
// {2t4,2t4+1,2t4+8,2t4+9} x two k16-steps are 16B contiguous.
__device__ __forceinline__ int pos32(int k5) {
    return ((k5 >> 1) & 3) * 8 + (k5 >> 4) * 4 + ((k5 >> 3) & 1) * 2 + (k5 & 1);
}
__device__ __forceinline__ int invpos32(int p) {
    return (((p >> 2) & 1) << 4) | (((p >> 1) & 1) << 3) | (((p >> 3) & 3) << 1) | (p & 1);
}

#define MBARRIER_INIT(mbar, cnt) \
    asm volatile("mbarrier.init.shared.b64 [%0], %1;" \
                 :: "r"((uint32_t)(mbar)), "r"((uint32_t)(cnt)) : "memory")
#define MBARRIER_EXPECT_TX(mbar, bytes) \
    asm volatile("mbarrier.arrive.expect_tx.shared.b64 _, [%0], %1;" \
                 :: "r"((uint32_t)(mbar)), "r"((uint32_t)(bytes)) : "memory")
#define MBARRIER_WAIT_PARITY(mbar_a, par) do { \
    uint32_t _m = (uint32_t)(mbar_a), _p = (uint32_t)(par), _d; \
    asm volatile("{\n\t.reg .pred p;\n\t" \
        "mbarrier.try_wait.parity.acquire.cta.shared::cta.b64 p, [%1], %2;\n\t" \
        "selp.b32 %0, 1, 0, p;\n\t}" : "=r"(_d) : "r"(_m), "r"(_p) : "memory"); \
    if (!_d) { \
        asm volatile("{\n\t.reg .pred P1;\n\t" \
            "WL_%=:\n\t" \
            "mbarrier.try_wait.parity.acquire.cta.shared::cta.b64 P1, [%0], %1, 0x989680;\n\t" \
            "@P1 bra.uni WD_%=;\n\t" \
            "bra.uni WL_%=;\n\t" \
            "WD_%=:\n\t}" :: "r"(_m), "r"(_p) : "memory"); \
    } \
} while (0)
#define BULK_G2S(dst_u32, src_ptr, bytes, mbar_u32) \
    asm volatile("cp.async.bulk.shared::cta.global.mbarrier::complete_tx::bytes " \
                 "[%0], [%1], %2, [%3];" \
                 :: "r"(dst_u32), "l"(src_ptr), "r"((uint32_t)(bytes)), \
                    "r"(mbar_u32) : "memory")

// ---------------- init: interleaved fp16 store ----------------
__global__ void init_gather(const int* __restrict__ thax,
                            const float* __restrict__ table) {
    int t = blockIdx.x * blockDim.x + threadIdx.x;
    int row = t >> 6, c = t & 63;
    if (row < N0) {
        int tid_ = thax[row];
        float4 v = ((const float4*)(table + (size_t)tid_ * D))[c];
        int k = c * 4;
        __half* hdst = g_storeh + (size_t)row * D + (k >> 5) * 32;
        int k5 = k & 31;
        *(__half2*)(hdst + pos32(k5))     = __floats2half2_rn(v.x, v.y);
        *(__half2*)(hdst + pos32(k5 + 2)) = __floats2half2_rn(v.z, v.w);
    }
}

// ---------------- weight convert ----------------
// W[R][K][256] -> Wt stage-contiguous: [R][h(2)][s(K/32)][n(128)][k(32 interleaved)]
template<int K, bool FIRST>
__global__ void convert_w(const float* __restrict__ W) {
    int s = blockIdx.x, r = blockIdx.y, c = threadIdx.x;
    int h = c >> 7, n = c & 127;
    const float* Wr = W + ((size_t)r * K + s * 32) * D + h * 128 + n;
    __half loc[32];
#pragma unroll
    for (int k5 = 0; k5 < 32; k5++)
        loc[pos32(k5)] = __float2half_rn(Wr[(size_t)k5 * D]);
    __half* dst = (FIRST ? g_W1h : g_W2h)
                + ((size_t)((r * 2 + h) * (K / 32) + s) * 128 + n) * 32;
    uint4* d4 = (uint4*)dst;
    const uint4* s4 = (const uint4*)loc;
#pragma unroll
    for (int i = 0; i < 4; i++) d4[i] = s4[i];
}

// ---------------- fused layer: 512 thr, 16 warps (2m x 8n), grid 128 ----------------
// GEMM1: Hs(smem) = relu(gather(par)[64xK1] @ W1[r] + b1)
// GEMM2: g_storeh[N0+l*NL+m] = Hs @ W2[r] + b2
// A resident (64 x AS), B: unified 4-slot ring of 16KB bulk stages (W1 then W2).
__global__ void __launch_bounds__(512, 1)
layer_fused(const float* __restrict__ b1, const float* __restrict__ b2,
            const int* __restrict__ par, int layer) {
    extern __shared__ __half sm[];
    __shared__ __align__(8) uint64_t mbars[5];   // [0..3] ring, [4] A
    __half* smB = sm + OFF_B;
    __half* Hs  = sm + OFF_H;
    const uint32_t smAu = smem_to_u32(sm);
    const uint32_t smBu = smem_to_u32(smB);
    const uint32_t mbarA = smem_to_u32(&mbars[4]);

    const int tid  = threadIdx.x;
    const int lane = tid & 31;
    const int wid  = tid >> 5;
    const int g    = lane >> 2, t4 = lane & 3;
    const int warp_m = wid >> 3, warp_n = wid & 7;   // 2 x 8, warp tile 32x32
    const int m0 = blockIdx.x * 64;
    const int r  = blockIdx.x >> 3;

    const __half* W1r = g_W1h + (size_t)(r * 2 * NIT1) * 4096;
    const __half* W2r = g_W2h + (size_t)(r * 2 * NIT2) * 4096;

    // unified B stage: s<NIT1 -> W1 stage s; else W2 stage s-NIT1. 2 x 8KB per stage.
    auto issueB = [&](int s) {
        uint32_t mb = smem_to_u32(&mbars[s & 3]);
        MBARRIER_EXPECT_TX(mb, 16384);
        uint32_t dst = smBu + (uint32_t)((s & 3) * 8192) * 2u;
        if (s < NIT1) {
            BULK_G2S(dst,        W1r + (size_t)s * 4096,               8192, mb);
            BULK_G2S(dst + 8192, W1r + (size_t)(NIT1 + s) * 4096,      8192, mb);
        } else {
            int s2 = s - NIT1;
            BULK_G2S(dst,        W2r + (size_t)s2 * 4096,              8192, mb);
            BULK_G2S(dst + 8192, W2r + (size_t)(NIT2 + s2) * 4096,     8192, mb);
        }
    };

    if (tid == 0) {
#pragma unroll
        for (int i = 0; i < 5; i++) MBARRIER_INIT(smem_to_u32(&mbars[i]), 1);
        asm volatile("fence.proxy.async.shared::cta;" ::: "memory");
    }
    __syncthreads();

    // A gather: 128 bulk copies of 512B (row, parent-half)
    if (tid == 0) MBARRIER_EXPECT_TX(mbarA, 64 * 1024);
    __syncthreads();
    if (tid < 128) {
        int row = tid >> 1, p = tid & 1;
        const __half* src = g_storeh + (size_t)par[2 * (m0 + row) + p] * D;
        BULK_G2S(smAu + (uint32_t)(row * AS + p * 256) * 2u, src, 512, mbarA);
    }
    if (tid == 0) { issueB(0); issueB(1); issueB(2); }

    float acc[2][4][4];
#pragma unroll
    for (int mt = 0; mt < 2; mt++)
#pragma unroll
        for (int nt = 0; nt < 4; nt++)
#pragma unroll
            for (int c = 0; c < 4; c++) acc[mt][nt][c] = 0.f;

    // one stage of one GEMM: warp tile 32x32, 8 LDS.128 + 16 HMMA
    auto do_stage = [&](const __half* Arow0, int astr, int koff, const __half* Bs) {
        uint4 Av[2][2];
#pragma unroll
        for (int mt = 0; mt < 2; mt++) {
            const __half* ab = Arow0 + (warp_m * 32 + mt * 16 + g) * astr + koff + t4 * 8;
            Av[mt][0] = *(const uint4*)ab;
            Av[mt][1] = *(const uint4*)(ab + 8 * astr);
        }
        uint4 Bv[4];
#pragma unroll
        for (int nt = 0; nt < 4; nt++) {
            int cc = warp_n * 32 + nt * 8 + g;
            Bv[nt] = *(const uint4*)(Bs + cc * 32 + t4 * 8);
        }
#pragma unroll
        for (int step = 0; step < 2; step++) {
#pragma unroll
            for (int mt = 0; mt < 2; mt++) {
                uint32_t a0 = step ? Av[mt][0].z : Av[mt][0].x;
                uint32_t a1 = step ? Av[mt][1].z : Av[mt][1].x;
                uint32_t a2 = step ? Av[mt][0].w : Av[mt][0].y;
                uint32_t a3 = step ? Av[mt][1].w : Av[mt][1].y;
#pragma unroll
                for (int nt = 0; nt < 4; nt++) {
                    uint32_t b0 = step ? Bv[nt].z : Bv[nt].x;
                    uint32_t b1r = step ? Bv[nt].w : Bv[nt].y;
                    asm volatile(
                        "mma.sync.aligned.m16n8k16.row.col.f32.f16.f16.f32 "
                        "{%0,%1,%2,%3}, {%4,%5,%6,%7}, {%8,%9}, {%0,%1,%2,%3};"
                        : "+f"(acc[mt][nt][0]), "+f"(acc[mt][nt][1]),
                          "+f"(acc[mt][nt][2]), "+f"(acc[mt][nt][3])
                        : "r"(a0), "r"(a1), "r"(a2), "r"(a3), "r"(b0), "r"(b1r));
                }
            }
        }
    };

    // ================= GEMM1 =================
    for (int it = 0; it < NIT1; it++) {
        __syncthreads();                          // slot (it+3)&3 readers done
        if (tid == 0 && it + 3 < NIT1 + 3) issueB(it + 3);   // stages 3..18
        if (it == 0) MBARRIER_WAIT_PARITY(mbarA, 0);
        MBARRIER_WAIT_PARITY(smem_to_u32(&mbars[it & 3]), (it >> 2) & 1);
        do_stage(sm, AS, it * 32, smB + (it & 3) * 8192);
    }

    // ---- H epilogue: bias1 + relu -> Hs (interleaved, stride HS) ----
    {
        const float* br = b1 + r * D;
#pragma unroll
        for (int mt = 0; mt < 2; mt++) {
            int rA = warp_m * 32 + mt * 16 + g;
#pragma unroll
            for (int nt = 0; nt < 4; nt++) {
                int col = warp_n * 32 + nt * 8 + 2 * t4;
                float bx = br[col], by = br[col + 1];
                float x0 = fmaxf(acc[mt][nt][0] + bx, 0.f);
                float y0 = fmaxf(acc[mt][nt][1] + by, 0.f);
                float x1 = fmaxf(acc[mt][nt][2] + bx, 0.f);
                float y1 = fmaxf(acc[mt][nt][3] + by, 0.f);
                int hoff = (col >> 5) * 32 + pos32(col & 31);
                *(__half2*)(Hs + rA * HS + hoff)       = __floats2half2_rn(x0, y0);
                *(__half2*)(Hs + (rA + 8) * HS + hoff) = __floats2half2_rn(x1, y1);
            }
        }
    }

    // ================= GEMM2 (A = Hs) =================
#pragma unroll
    for (int mt = 0; mt < 2; mt++)
#pragma unroll
        for (int nt = 0; nt < 4; nt++)
#pragma unroll
            for (int c = 0; c < 4; c++) acc[mt][nt][c] = 0.f;

    for (int s = 0; s < NIT2; s++) {
        int gs = NIT1 + s;
        __syncthreads();                          // H visible (s=0); ring slot free
        if (tid == 0 && gs + 3 < NSTG) issueB(gs + 3);
        MBARRIER_WAIT_PARITY(smem_to_u32(&mbars[gs & 3]), (gs >> 2) & 1);
        do_stage(Hs, HS, s * 32, smB + (gs & 3) * 8192);
    }

    // ---- final epilogue: bias2 -> g_storeh interleaved ----
    {
        __half* Cbase = g_storeh + (size_t)(N0 + layer * NL) * D;
        const float* br = b2 + r * D;
#pragma unroll
        for (int mt = 0; mt < 2; mt++) {
            int mr0 = m0 + warp_m * 32 + mt * 16 + g;
#pragma unroll
            for (int nt = 0; nt < 4; nt++) {
                int col = warp_n * 32 + nt * 8 + 2 * t4;
                float bx = br[col], by = br[col + 1];
                float x0 = acc[mt][nt][0] + bx, y0 = acc[mt][nt][1] + by;
                float x1 = acc[mt][nt][2] + bx, y1 = acc[mt][nt][3] + by;
                int hoff = (col >> 5) * 32 + pos32(col & 31);
                *(__half2*)(Cbase + (size_t)mr0 * D + hoff)       = __floats2half2_rn(x0, y0);
                *(__half2*)(Cbase + (size_t)(mr0 + 8) * D + hoff) = __floats2half2_rn(x1, y1);
            }
        }
    }
}

// ---------------- eval + loss from fp16 interleaved store ----------------
__device__ __forceinline__ float softplusf(float x) {
    return fmaxf(x, 0.f) + log1pf(expf(-fabsf(x)));
}

__global__ void __launch_bounds__(256)
eval_partial(const float* __restrict__ pos_vals, const float* __restrict__ neg_vals,
             const float* __restrict__ eval_w, const float* __restrict__ eval_b,
             const float* __restrict__ pos_weight) {
    __shared__ float red[8][5];
    const int lane = threadIdx.x & 31, warp = threadIdx.x >> 5;
    const int gw = blockIdx.x * 8 + warp;

    float w[8];
#pragma unroll
    for (int j = 0; j < 8; j++) {
        int q = lane * 8 + j;
        int k = (q >> 5) * 32 + invpos32(q & 31);
        w[j] = eval_w[k];
    }
    const float eb = *eval_b;
    const float pw = *pos_weight;

    float loss = 0.f, posOK = 0.f, negOK = 0.f, posTot = 0.f, negTot = 0.f;

    for (int node = gw; node < TOTAL; node += EVAL_BLOCKS * 8) {
        const __half2* row = (const __half2*)(g_storeh + (size_t)node * D);
        float s = 0.f;
#pragma unroll
        for (int i = 0; i < 4; i++) {
            float2 v = __half22float2(row[lane * 4 + i]);
            s += v.x * w[2 * i] + v.y * w[2 * i + 1];
        }
#pragma unroll
        for (int off = 16; off; off >>= 1) s += __shfl_xor_sync(0xffffffffu, s, off);
        if (lane == 0) {
            float x = s + eb;
            float pv = pos_vals[node], nv = neg_vals[node];
            float tot = pv + nv;
            if (tot > 0.f) {
                float tgt = pv / fmaxf(tot, 1e-9f);
                float bce = pw * tgt * softplusf(-x) + (1.f - tgt) * softplusf(x);
                loss += tot * bce;
                posTot += pv; negTot += nv;
                if (x >= 0.f) posOK += pv; else negOK += nv;
            }
        }
    }
    if (lane == 0) {
        red[warp][0] = loss; red[warp][1] = posOK; red[warp][2] = negOK;
        red[warp][3] = posTot; red[warp][4] = negTot;
    }
    __syncthreads();
    if (threadIdx.x < 5) {
        float t = 0.f;
        for (int i = 0; i < 8; i++) t += red[i][threadIdx.x];
        g_partials[blockIdx.x * 5 + threadIdx.x] = t;
    }
}

__global__ void final_reduce(float* __restrict__ out, int out_size) {
    float s[5] = {0.f, 0.f, 0.f, 0.f, 0.f};
    for (int i = threadIdx.x; i < EVAL_BLOCKS; i += 32)
#pragma unroll
        for (int c = 0; c < 5; c++) s[c] += g_partials[i * 5 + c];
#pragma unroll
    for (int c = 0; c < 5; c++)
#pragma unroll
        for (int off = 16; off; off >>= 1)
            s[c] += __shfl_xor_sync(0xffffffffu, s[c], off);
    if (threadIdx.x == 0) {
        float loss = s[0], posOK = s[1], negOK = s[2], posTot = s[3], negTot = s[4];
        float pos_rate = (posTot > 0.f) ? posOK / fmaxf(posTot, 1e-9f) : 1.f;
        float neg_rate = (negTot > 0.f) ? negOK / fmaxf(negTot, 1e-9f) : 1.f;
        if (out_size >= 1) out[0] = loss;
        if (out_size >= 2) out[1] = pos_rate;
        if (out_size >= 3) out[2] = neg_rate;
    }
}

// ---------------- launch ----------------
extern "C" void kernel_launch(void* const* d_in, const int* in_sizes, int n_in,
                              void* d_out, int out_size) {
    const int*   thax       = (const int*)  d_in[0];
    const int*   par_idx    = (const int*)  d_in[1];
    const float* pos_vals   = (const float*)d_in[2];
    const float* neg_vals   = (const float*)d_in[3];
    const float* init_table = (const float*)d_in[4];
    const float* W1         = (const float*)d_in[5];
    const float* b1         = (const float*)d_in[6];
    const float* W2         = (const float*)d_in[7];
    const float* b2         = (const float*)d_in[8];
    const float* eval_w     = (const float*)d_in[9];
    const float* eval_b     = (const float*)d_in[10];
    const float* pos_weight = (const float*)d_in[11];
    float* out = (float*)d_out;

    cudaFuncSetAttribute(layer_fused,
                         cudaFuncAttributeMaxDynamicSharedMemorySize, SMEM_BYTES);

    init_gather<<<(N0 * 64) / 256, 256>>>(thax, init_table);
    convert_w<K1, true ><<<dim3(K1 / 32, R), 256>>>(W1);
    convert_w<K2, false><<<dim3(K2 / 32, R), 256>>>(W2);

    for (int l = 0; l < L; l++) {
        layer_fused<<<NL / 64, 512, SMEM_BYTES>>>(
            b1, b2, par_idx + (size_t)l * NL * 2, l);
    }

    eval_partial<<<EVAL_BLOCKS, 256>>>(pos_vals, neg_vals, eval_w, eval_b, pos_weight);
    final_reduce<<<1, 32>>>(out, out_size);
}

// round 11
// speedup vs baseline: 1.4851x; 1.1068x over previous
#include <cuda_runtime.h>
#include <cuda_fp16.h>
#include <math.h>
#include <cstdint>

#define D      256
#define R      16
#define N0     8192
#define L      6
#define NL     8192
#define TOTAL  (N0 + L * NL)   // 57344
#define EVAL_BLOCKS 224

#define K1 512
#define K2 256
#define NS1  8                 // K1/64 superstages
#define NS2  4                 // K2/64
#define NSTG (NS1 + NS2)       // 12

// smem layout (halfs)
#define AS     544             // A row stride (K1+32): conflict-free LDS.128 phases
#define HS     288             // H row stride: conflict-free
#define OFF_B  (64 * AS)                  // 34816
#define SLOT   16384                      // one 64k superstage: [sub(2)][h(2)][128n][32k]
#define OFF_H  (OFF_B + 3 * SLOT)         // 83968
#define SMEM_HALFS (OFF_H + 64 * HS)      // 102400
#define SMEM_BYTES (SMEM_HALFS * 2)       // 204800

// ---------------- scratch (device globals; no allocation) ----------------
__device__ __half g_storeh[(size_t)TOTAL * D];    // fp16 k-interleaved embeddings
__device__ __half g_W1h[(size_t)R * D * K1];      // stage-contiguous fp16 W1^T
__device__ __half g_W2h[(size_t)R * D * K2];
__device__ float  g_partials[EVAL_BLOCKS * 5];

__device__ __forceinline__ uint32_t smem_to_u32(const void* p) {
    uint32_t a;
    asm("{ .reg .u64 t; cvta.to.shared.u64 t, %1; cvt.u32.u64 %0, t; }" : "=r"(a) : "l"(p));
    return a;
}

// interleave position of k within a 32-k group: thread t4's fragment halves
// {2t4,2t4+1,2t4+8,2t4+9} x two k16-steps are 16B contiguous.
__device__ __forceinline__ int pos32(int k5) {
    return ((k5 >> 1) & 3) * 8 + (k5 >> 4) * 4 + ((k5 >> 3) & 1) * 2 + (k5 & 1);
}
__device__ __forceinline__ int invpos32(int p) {
    return (((p >> 2) & 1) << 4) | (((p >> 1) & 1) << 3) | (((p >> 3) & 3) << 1) | (p & 1);
}

#define MBARRIER_INIT(mbar, cnt) \
    asm volatile("mbarrier.init.shared.b64 [%0], %1;" \
                 :: "r"((uint32_t)(mbar)), "r"((uint32_t)(cnt)) : "memory")
#define MBARRIER_EXPECT_TX(mbar, bytes) \
    asm volatile("mbarrier.arrive.expect_tx.shared.b64 _, [%0], %1;" \
                 :: "r"((uint32_t)(mbar)), "r"((uint32_t)(bytes)) : "memory")
#define MBARRIER_WAIT_PARITY(mbar_a, par) do { \
    uint32_t _m = (uint32_t)(mbar_a), _p = (uint32_t)(par), _d; \
    asm volatile("{\n\t.reg .pred p;\n\t" \
        "mbarrier.try_wait.parity.acquire.cta.shared::cta.b64 p, [%1], %2;\n\t" \
        "selp.b32 %0, 1, 0, p;\n\t}" : "=r"(_d) : "r"(_m), "r"(_p) : "memory"); \
    if (!_d) { \
        asm volatile("{\n\t.reg .pred P1;\n\t" \
            "WL_%=:\n\t" \
            "mbarrier.try_wait.parity.acquire.cta.shared::cta.b64 P1, [%0], %1, 0x989680;\n\t" \
            "@P1 bra.uni WD_%=;\n\t" \
            "bra.uni WL_%=;\n\t" \
            "WD_%=:\n\t}" :: "r"(_m), "r"(_p) : "memory"); \
    } \
} while (0)
#define BULK_G2S(dst_u32, src_ptr, bytes, mbar_u32) \
    asm volatile("cp.async.bulk.shared::cta.global.mbarrier::complete_tx::bytes " \
                 "[%0], [%1], %2, [%3];" \
                 :: "r"(dst_u32), "l"(src_ptr), "r"((uint32_t)(bytes)), \
                    "r"(mbar_u32) : "memory")

// ---------------- init: interleaved fp16 store ----------------
__global__ void init_gather(const int* __restrict__ thax,
                            const float* __restrict__ table) {
    int t = blockIdx.x * blockDim.x + threadIdx.x;
    int row = t >> 6, c = t & 63;
    if (row < N0) {
        int tid_ = thax[row];
        float4 v = ((const float4*)(table + (size_t)tid_ * D))[c];
        int k = c * 4;
        __half* hdst = g_storeh + (size_t)row * D + (k >> 5) * 32;
        int k5 = k & 31;
        *(__half2*)(hdst + pos32(k5))     = __floats2half2_rn(v.x, v.y);
        *(__half2*)(hdst + pos32(k5 + 2)) = __floats2half2_rn(v.z, v.w);
    }
}

// ---------------- weight convert ----------------
// W[R][K][256] -> Wt stage-contiguous: [R][h(2)][s(K/32)][n(128)][k(32 interleaved)]
template<int K, bool FIRST>
__global__ void convert_w(const float* __restrict__ W) {
    int s = blockIdx.x, r = blockIdx.y, c = threadIdx.x;
    int h = c >> 7, n = c & 127;
    const float* Wr = W + ((size_t)r * K + s * 32) * D + h * 128 + n;
    __half loc[32];
#pragma unroll
    for (int k5 = 0; k5 < 32; k5++)
        loc[pos32(k5)] = __float2half_rn(Wr[(size_t)k5 * D]);
    __half* dst = (FIRST ? g_W1h : g_W2h)
                + ((size_t)((r * 2 + h) * (K / 32) + s) * 128 + n) * 32;
    uint4* d4 = (uint4*)dst;
    const uint4* s4 = (const uint4*)loc;
#pragma unroll
    for (int i = 0; i < 4; i++) d4[i] = s4[i];
}

// ---------------- fused layer: 512 thr, 16 warps (2m x 8n), grid 128 ----------------
// GEMM1: Hs(smem) = relu(gather(par)[64xK1] @ W1[r] + b1)
// GEMM2: g_storeh[N0+l*NL+m] = Hs @ W2[r] + b2
// A resident (64 x AS); B: ring of 3 x 32KB superstages (BK=64), 4 bulk copies each.
__global__ void __launch_bounds__(512, 1)
layer_fused(const float* __restrict__ b1, const float* __restrict__ b2,
            const int* __restrict__ par, int layer) {
    extern __shared__ __half sm[];
    __shared__ __align__(8) uint64_t mbars[4];   // [0..2] ring, [3] A
    __half* smB = sm + OFF_B;
    __half* Hs  = sm + OFF_H;
    const uint32_t smAu = smem_to_u32(sm);
    const uint32_t smBu = smem_to_u32(smB);
    const uint32_t mbarA = smem_to_u32(&mbars[3]);

    const int tid  = threadIdx.x;
    const int lane = tid & 31;
    const int wid  = tid >> 5;
    const int g    = lane >> 2, t4 = lane & 3;
    const int warp_m = wid >> 3, warp_n = wid & 7;   // 2 x 8, warp tile 32x32
    const int m0 = blockIdx.x * 64;
    const int r  = blockIdx.x >> 3;

    // W layout: [r][h(2)][s32][128n][32k]; h-stride = (K/32) 4096-half units
    const __half* W1r = g_W1h + (size_t)(r * 2 * (K1 / 32)) * 4096;
    const __half* W2r = g_W2h + (size_t)(r * 2 * (K2 / 32)) * 4096;

    // superstage s (64k): covers 32k-stages {2s, 2s+1}; slot layout:
    //   +0: sub0 h0, +4096: sub0 h1, +8192: sub1 h0, +12288: sub1 h1
    auto issueB = [&](int s) {
        uint32_t mb = smem_to_u32(&mbars[s % 3]);
        MBARRIER_EXPECT_TX(mb, 4 * 8192);
        uint32_t dst = smBu + (uint32_t)((s % 3) * SLOT) * 2u;
        const __half* Wr_;
        int hstride, s32;
        if (s < NS1) { Wr_ = W1r; hstride = K1 / 32; s32 = 2 * s; }
        else         { Wr_ = W2r; hstride = K2 / 32; s32 = 2 * (s - NS1); }
        BULK_G2S(dst,                 Wr_ + (size_t)s32 * 4096,             8192, mb);
        BULK_G2S(dst + 2 * 4096,      Wr_ + (size_t)(hstride + s32) * 4096, 8192, mb);
        BULK_G2S(dst + 2 * 8192,      Wr_ + (size_t)(s32 + 1) * 4096,       8192, mb);
        BULK_G2S(dst + 2 * 12288,     Wr_ + (size_t)(hstride + s32 + 1) * 4096, 8192, mb);
    };

    if (tid == 0) {
#pragma unroll
        for (int i = 0; i < 4; i++) MBARRIER_INIT(smem_to_u32(&mbars[i]), 1);
        asm volatile("fence.proxy.async.shared::cta;" ::: "memory");
    }
    __syncthreads();

    // A gather: 128 bulk copies of 512B (row, parent-half)
    if (tid == 0) MBARRIER_EXPECT_TX(mbarA, 64 * 1024);
    __syncthreads();
    if (tid < 128) {
        int row = tid >> 1, p = tid & 1;
        const __half* src = g_storeh + (size_t)par[2 * (m0 + row) + p] * D;
        BULK_G2S(smAu + (uint32_t)(row * AS + p * 256) * 2u, src, 512, mbarA);
    }
    if (tid == 0) { issueB(0); issueB(1); }

    float acc[2][4][4];
#pragma unroll
    for (int mt = 0; mt < 2; mt++)
#pragma unroll
        for (int nt = 0; nt < 4; nt++)
#pragma unroll
            for (int c = 0; c < 4; c++) acc[mt][nt][c] = 0.f;

    // one 32k sub-stage: warp tile 32x32, 8 LDS.128 + 16 HMMA
    auto do_sub = [&](const __half* Arow0, int astr, int koff, const __half* Bs) {
        uint4 Av[2][2];
#pragma unroll
        for (int mt = 0; mt < 2; mt++) {
            const __half* ab = Arow0 + (warp_m * 32 + mt * 16 + g) * astr + koff + t4 * 8;
            Av[mt][0] = *(const uint4*)ab;
            Av[mt][1] = *(const uint4*)(ab + 8 * astr);
        }
        uint4 Bv[4];
#pragma unroll
        for (int nt = 0; nt < 4; nt++) {
            int cc = warp_n * 32 + nt * 8 + g;
            Bv[nt] = *(const uint4*)(Bs + cc * 32 + t4 * 8);
        }
#pragma unroll
        for (int step = 0; step < 2; step++) {
#pragma unroll
            for (int mt = 0; mt < 2; mt++) {
                uint32_t a0 = step ? Av[mt][0].z : Av[mt][0].x;
                uint32_t a1 = step ? Av[mt][1].z : Av[mt][1].x;
                uint32_t a2 = step ? Av[mt][0].w : Av[mt][0].y;
                uint32_t a3 = step ? Av[mt][1].w : Av[mt][1].y;
#pragma unroll
                for (int nt = 0; nt < 4; nt++) {
                    uint32_t b0 = step ? Bv[nt].z : Bv[nt].x;
                    uint32_t b1r = step ? Bv[nt].w : Bv[nt].y;
                    asm volatile(
                        "mma.sync.aligned.m16n8k16.row.col.f32.f16.f16.f32 "
                        "{%0,%1,%2,%3}, {%4,%5,%6,%7}, {%8,%9}, {%0,%1,%2,%3};"
                        : "+f"(acc[mt][nt][0]), "+f"(acc[mt][nt][1]),
                          "+f"(acc[mt][nt][2]), "+f"(acc[mt][nt][3])
                        : "r"(a0), "r"(a1), "r"(a2), "r"(a3), "r"(b0), "r"(b1r));
                }
            }
        }
    };

    // ================= GEMM1: superstages 0..NS1-1 =================
#pragma unroll
    for (int s = 0; s < NS1; s++) {
        __syncthreads();                          // slot (s+2)%3 readers done
        if (tid == 0 && s + 2 < NSTG) issueB(s + 2);
        if (s == 0) MBARRIER_WAIT_PARITY(mbarA, 0);
        MBARRIER_WAIT_PARITY(smem_to_u32(&mbars[s % 3]), (s / 3) & 1);
        const __half* Bs = smB + (s % 3) * SLOT;
        do_sub(sm, AS, s * 64,      Bs);
        do_sub(sm, AS, s * 64 + 32, Bs + 8192);
    }

    // ---- H epilogue: bias1 + relu -> Hs (interleaved, stride HS) ----
    {
        const float* br = b1 + r * D;
#pragma unroll
        for (int mt = 0; mt < 2; mt++) {
            int rA = warp_m * 32 + mt * 16 + g;
#pragma unroll
            for (int nt = 0; nt < 4; nt++) {
                int col = warp_n * 32 + nt * 8 + 2 * t4;
                float bx = br[col], by = br[col + 1];
                float x0 = fmaxf(acc[mt][nt][0] + bx, 0.f);
                float y0 = fmaxf(acc[mt][nt][1] + by, 0.f);
                float x1 = fmaxf(acc[mt][nt][2] + bx, 0.f);
                float y1 = fmaxf(acc[mt][nt][3] + by, 0.f);
                int hoff = (col >> 5) * 32 + pos32(col & 31);
                *(__half2*)(Hs + rA * HS + hoff)       = __floats2half2_rn(x0, y0);
                *(__half2*)(Hs + (rA + 8) * HS + hoff) = __floats2half2_rn(x1, y1);
            }
        }
    }

    // ================= GEMM2: superstages NS1..NSTG-1 (A = Hs) =================
#pragma unroll
    for (int mt = 0; mt < 2; mt++)
#pragma unroll
        for (int nt = 0; nt < 4; nt++)
#pragma unroll
            for (int c = 0; c < 4; c++) acc[mt][nt][c] = 0.f;

#pragma unroll
    for (int s2 = 0; s2 < NS2; s2++) {
        int gs = NS1 + s2;
        __syncthreads();                          // H visible (s2=0); ring slot free
        if (tid == 0 && gs + 2 < NSTG) issueB(gs + 2);
        MBARRIER_WAIT_PARITY(smem_to_u32(&mbars[gs % 3]), (gs / 3) & 1);
        const __half* Bs = smB + (gs % 3) * SLOT;
        do_sub(Hs, HS, s2 * 64,      Bs);
        do_sub(Hs, HS, s2 * 64 + 32, Bs + 8192);
    }

    // ---- final epilogue: bias2 -> g_storeh interleaved ----
    {
        __half* Cbase = g_storeh + (size_t)(N0 + layer * NL) * D;
        const float* br = b2 + r * D;
#pragma unroll
        for (int mt = 0; mt < 2; mt++) {
            int mr0 = m0 + warp_m * 32 + mt * 16 + g;
#pragma unroll
            for (int nt = 0; nt < 4; nt++) {
                int col = warp_n * 32 + nt * 8 + 2 * t4;
                float bx = br[col], by = br[col + 1];
                float x0 = acc[mt][nt][0] + bx, y0 = acc[mt][nt][1] + by;
                float x1 = acc[mt][nt][2] + bx, y1 = acc[mt][nt][3] + by;
                int hoff = (col >> 5) * 32 + pos32(col & 31);
                *(__half2*)(Cbase + (size_t)mr0 * D + hoff)       = __floats2half2_rn(x0, y0);
                *(__half2*)(Cbase + (size_t)(mr0 + 8) * D + hoff) = __floats2half2_rn(x1, y1);
            }
        }
    }
}

// ---------------- eval + loss from fp16 interleaved store ----------------
__device__ __forceinline__ float softplusf(float x) {
    return fmaxf(x, 0.f) + log1pf(expf(-fabsf(x)));
}

__global__ void __launch_bounds__(256)
eval_partial(const float* __restrict__ pos_vals, const float* __restrict__ neg_vals,
             const float* __restrict__ eval_w, const float* __restrict__ eval_b,
             const float* __restrict__ pos_weight) {
    __shared__ float red[8][5];
    const int lane = threadIdx.x & 31, warp = threadIdx.x >> 5;
    const int gw = blockIdx.x * 8 + warp;

    float w[8];
#pragma unroll
    for (int j = 0; j < 8; j++) {
        int q = lane * 8 + j;
        int k = (q >> 5) * 32 + invpos32(q & 31);
        w[j] = eval_w[k];
    }
    const float eb = *eval_b;
    const float pw = *pos_weight;

    float loss = 0.f, posOK = 0.f, negOK = 0.f, posTot = 0.f, negTot = 0.f;

    for (int node = gw; node < TOTAL; node += EVAL_BLOCKS * 8) {
        const __half2* row = (const __half2*)(g_storeh + (size_t)node * D);
        float s = 0.f;
#pragma unroll
        for (int i = 0; i < 4; i++) {
            float2 v = __half22float2(row[lane * 4 + i]);
            s += v.x * w[2 * i] + v.y * w[2 * i + 1];
        }
#pragma unroll
        for (int off = 16; off; off >>= 1) s += __shfl_xor_sync(0xffffffffu, s, off);
        if (lane == 0) {
            float x = s + eb;
            float pv = pos_vals[node], nv = neg_vals[node];
            float tot = pv + nv;
            if (tot > 0.f) {
                float tgt = pv / fmaxf(tot, 1e-9f);
                float bce = pw * tgt * softplusf(-x) + (1.f - tgt) * softplusf(x);
                loss += tot * bce;
                posTot += pv; negTot += nv;
                if (x >= 0.f) posOK += pv; else negOK += nv;
            }
        }
    }
    if (lane == 0) {
        red[warp][0] = loss; red[warp][1] = posOK; red[warp][2] = negOK;
        red[warp][3] = posTot; red[warp][4] = negTot;
    }
    __syncthreads();
    if (threadIdx.x < 5) {
        float t = 0.f;
        for (int i = 0; i < 8; i++) t += red[i][threadIdx.x];
        g_partials[blockIdx.x * 5 + threadIdx.x] = t;
    }
}

__global__ void final_reduce(float* __restrict__ out, int out_size) {
    float s[5] = {0.f, 0.f, 0.f, 0.f, 0.f};
    for (int i = threadIdx.x; i < EVAL_BLOCKS; i += 32)
#pragma unroll
        for (int c = 0; c < 5; c++) s[c] += g_partials[i * 5 + c];
#pragma unroll
    for (int c = 0; c < 5; c++)
#pragma unroll
        for (int off = 16; off; off >>= 1)
            s[c] += __shfl_xor_sync(0xffffffffu, s[c], off);
    if (threadIdx.x == 0) {
        float loss = s[0], posOK = s[1], negOK = s[2], posTot = s[3], negTot = s[4];
        float pos_rate = (posTot > 0.f) ? posOK / fmaxf(posTot, 1e-9f) : 1.f;
        float neg_rate = (negTot > 0.f) ? negOK / fmaxf(negTot, 1e-9f) : 1.f;
        if (out_size >= 1) out[0] = loss;
        if (out_size >= 2) out[1] = pos_rate;
        if (out_size >= 3) out[2] = neg_rate;
    }
}

// ---------------- launch ----------------
extern "C" void kernel_launch(void* const* d_in, const int* in_sizes, int n_in,
                              void* d_out, int out_size) {
    const int*   thax       = (const int*)  d_in[0];
    const int*   par_idx    = (const int*)  d_in[1];
    const float* pos_vals   = (const float*)d_in[2];
    const float* neg_vals   = (const float*)d_in[3];
    const float* init_table = (const float*)d_in[4];
    const float* W1         = (const float*)d_in[5];
    const float* b1         = (const float*)d_in[6];
    const float* W2         = (const float*)d_in[7];
    const float* b2         = (const float*)d_in[8];
    const float* eval_w     = (const float*)d_in[9];
    const float* eval_b     = (const float*)d_in[10];
    const float* pos_weight = (const float*)d_in[11];
    float* out = (float*)d_out;

    cudaFuncSetAttribute(layer_fused,
                         cudaFuncAttributeMaxDynamicSharedMemorySize, SMEM_BYTES);

    init_gather<<<(N0 * 64) / 256, 256>>>(thax, init_table);
    convert_w<K1, true ><<<dim3(K1 / 32, R), 256>>>(W1);
    convert_w<K2, false><<<dim3(K2 / 32, R), 256>>>(W2);

    for (int l = 0; l < L; l++) {
        layer_fused<<<NL / 64, 512, SMEM_BYTES>>>(
            b1, b2, par_idx + (size_t)l * NL * 2, l);
    }

    eval_partial<<<EVAL_BLOCKS, 256>>>(pos_vals, neg_vals, eval_w, eval_b, pos_weight);
    final_reduce<<<1, 32>>>(out, out_size);
}

// round 12
// speedup vs baseline: 1.5714x; 1.0581x over previous
#include <cuda_runtime.h>
#include <cuda_fp16.h>
#include <math.h>
#include <cstdint>

#define D      256
#define R      16
#define N0     8192
#define L      6
#define NL     8192
#define TOTAL  (N0 + L * NL)   // 57344
#define EVAL_BLOCKS 224

#define K1 512
#define K2 256
#define NS1  4                 // K1/128 superstages
#define NS2  2                 // K2/128
#define NSTG (NS1 + NS2)       // 6

// smem layout (halfs)
#define AS     544             // A row stride (K1+32): conflict-free LDS.128 phases
#define HS     288             // H row stride (aliases A region): conflict-free
#define OFF_B  (64 * AS)                  // 34816 halfs
#define SLOT   32768                      // 64KB superstage: [h(2)][sub(4)][128n][32k]
#define SMEM_HALFS (OFF_B + 2 * SLOT)     // 100352
#define SMEM_BYTES (SMEM_HALFS * 2)       // 200704

// ---------------- scratch (device globals; no allocation) ----------------
__device__ __half g_storeh[(size_t)TOTAL * D];    // fp16 k-interleaved embeddings
__device__ __half g_W1h[(size_t)R * D * K1];      // [r][h(2)][s32(16)][128n][32k]
__device__ __half g_W2h[(size_t)R * D * K2];      // [r][h(2)][s32(8)][128n][32k]
__device__ float  g_partials[EVAL_BLOCKS * 5];
__device__ int    g_evalcnt;                      // self-cleaning (reset by last block)

__device__ __forceinline__ uint32_t smem_to_u32(const void* p) {
    uint32_t a;
    asm("{ .reg .u64 t; cvta.to.shared.u64 t, %1; cvt.u32.u64 %0, t; }" : "=r"(a) : "l"(p));
    return a;
}

// interleave position of k within a 32-k group: thread t4's fragment halves
// {2t4,2t4+1,2t4+8,2t4+9} x two k16-steps are 16B contiguous.
__device__ __forceinline__ int pos32(int k5) {
    return ((k5 >> 1) & 3) * 8 + (k5 >> 4) * 4 + ((k5 >> 3) & 1) * 2 + (k5 & 1);
}
__device__ __forceinline__ int invpos32(int p) {
    return (((p >> 2) & 1) << 4) | (((p >> 1) & 1) << 3) | (((p >> 3) & 3) << 1) | (p & 1);
}

#define MBARRIER_INIT(mbar, cnt) \
    asm volatile("mbarrier.init.shared.b64 [%0], %1;" \
                 :: "r"((uint32_t)(mbar)), "r"((uint32_t)(cnt)) : "memory")
#define MBARRIER_EXPECT_TX(mbar, bytes) \
    asm volatile("mbarrier.arrive.expect_tx.shared.b64 _, [%0], %1;" \
                 :: "r"((uint32_t)(mbar)), "r"((uint32_t)(bytes)) : "memory")
#define MBARRIER_WAIT_PARITY(mbar_a, par) do { \
    uint32_t _m = (uint32_t)(mbar_a), _p = (uint32_t)(par), _d; \
    asm volatile("{\n\t.reg .pred p;\n\t" \
        "mbarrier.try_wait.parity.acquire.cta.shared::cta.b64 p, [%1], %2;\n\t" \
        "selp.b32 %0, 1, 0, p;\n\t}" : "=r"(_d) : "r"(_m), "r"(_p) : "memory"); \
    if (!_d) { \
        asm volatile("{\n\t.reg .pred P1;\n\t" \
            "WL_%=:\n\t" \
            "mbarrier.try_wait.parity.acquire.cta.shared::cta.b64 P1, [%0], %1, 0x989680;\n\t" \
            "@P1 bra.uni WD_%=;\n\t" \
            "bra.uni WL_%=;\n\t" \
            "WD_%=:\n\t}" :: "r"(_m), "r"(_p) : "memory"); \
    } \
} while (0)
#define BULK_G2S(dst_u32, src_ptr, bytes, mbar_u32) \
    asm volatile("cp.async.bulk.shared::cta.global.mbarrier::complete_tx::bytes " \
                 "[%0], [%1], %2, [%3];" \
                 :: "r"(dst_u32), "l"(src_ptr), "r"((uint32_t)(bytes)), \
                    "r"(mbar_u32) : "memory")

// ---------------- fused prologue: init gather + both weight converts ----------------
__device__ void convert_body(const float* __restrict__ W, __half* __restrict__ Wt,
                             int K, int s, int r, int tid) {
    int h = tid >> 7, n = tid & 127;
    const float* Wr = W + ((size_t)r * K + s * 32) * D + h * 128 + n;
    __half loc[32];
#pragma unroll
    for (int k5 = 0; k5 < 32; k5++)
        loc[pos32(k5)] = __float2half_rn(Wr[(size_t)k5 * D]);
    __half* dst = Wt + ((size_t)((r * 2 + h) * (K / 32) + s) * 128 + n) * 32;
    uint4* d4 = (uint4*)dst;
    const uint4* s4 = (const uint4*)loc;
#pragma unroll
    for (int i = 0; i < 4; i++) d4[i] = s4[i];
}

__global__ void __launch_bounds__(256)
prologue(const int* __restrict__ thax, const float* __restrict__ table,
         const float* __restrict__ W1, const float* __restrict__ W2) {
    int b = blockIdx.x;
    if (b < 2048) {                                   // init gather: N0*64 float4
        int t = b * 256 + threadIdx.x;
        int row = t >> 6, c = t & 63;
        int tid_ = thax[row];
        float4 v = ((const float4*)(table + (size_t)tid_ * D))[c];
        int k = c * 4;
        __half* hdst = g_storeh + (size_t)row * D + (k >> 5) * 32;
        int k5 = k & 31;
        *(__half2*)(hdst + pos32(k5))     = __floats2half2_rn(v.x, v.y);
        *(__half2*)(hdst + pos32(k5 + 2)) = __floats2half2_rn(v.z, v.w);
    } else if (b < 2048 + 256) {                      // W1: 16 s-groups x 16 rules
        int idx = b - 2048;
        convert_body(W1, g_W1h, K1, idx & 15, idx >> 4, threadIdx.x);
    } else {                                          // W2: 8 s-groups x 16 rules
        int idx = b - 2304;
        convert_body(W2, g_W2h, K2, idx & 7, idx >> 3, threadIdx.x);
    }
}

// ---------------- fused layer: 512 thr, 16 warps (2m x 8n), grid 128 ----------------
// GEMM1: Hs(smem, aliases A) = relu(gather(par)[64xK1] @ W1[r] + b1)
// GEMM2: g_storeh[N0+l*NL+m] = Hs @ W2[r] + b2
// A resident (64 x AS); B: ring of 2 x 64KB superstages (BK=128), 2 bulk copies each.
__global__ void __launch_bounds__(512, 1)
layer_fused(const float* __restrict__ b1, const float* __restrict__ b2,
            const int* __restrict__ par, int layer) {
    extern __shared__ __half sm[];
    __shared__ __align__(8) uint64_t mbars[3];   // [0,1] ring, [2] A
    __half* smB = sm + OFF_B;
    __half* Hs  = sm;                            // aliases A region (safe: see syncs)
    const uint32_t smAu = smem_to_u32(sm);
    const uint32_t smBu = smem_to_u32(smB);
    const uint32_t mbarA = smem_to_u32(&mbars[2]);

    const int tid  = threadIdx.x;
    const int lane = tid & 31;
    const int wid  = tid >> 5;
    const int g    = lane >> 2, t4 = lane & 3;
    const int warp_m = wid >> 3, warp_n = wid & 7;   // 2 x 8, warp tile 32x32
    const int m0 = blockIdx.x * 64;
    const int r  = blockIdx.x >> 3;

    const __half* W1r = g_W1h + (size_t)(r * 2 * (K1 / 32)) * 4096;
    const __half* W2r = g_W2h + (size_t)(r * 2 * (K2 / 32)) * 4096;

    // superstage s (128k) -> slot layout [h(2)][sub(4)][4096]; 2 x 32KB bulk copies
    auto issueB = [&](int s) {
        uint32_t mb = smem_to_u32(&mbars[s & 1]);
        MBARRIER_EXPECT_TX(mb, 65536);
        uint32_t dst = smBu + (uint32_t)((s & 1) * SLOT) * 2u;
        const __half* Wr_;
        int hstride, s32;
        if (s < NS1) { Wr_ = W1r; hstride = K1 / 32; s32 = 4 * s; }
        else         { Wr_ = W2r; hstride = K2 / 32; s32 = 4 * (s - NS1); }
        BULK_G2S(dst,             Wr_ + (size_t)s32 * 4096,             32768, mb);
        BULK_G2S(dst + 32768,     Wr_ + (size_t)(hstride + s32) * 4096, 32768, mb);
    };

    if (tid == 0) {
#pragma unroll
        for (int i = 0; i < 3; i++) MBARRIER_INIT(smem_to_u32(&mbars[i]), 1);
        asm volatile("fence.proxy.async.shared::cta;" ::: "memory");
    }
    __syncthreads();

    // A gather: 128 bulk copies of 512B (row, parent-half)
    if (tid == 0) MBARRIER_EXPECT_TX(mbarA, 64 * 1024);
    __syncthreads();
    if (tid < 128) {
        int row = tid >> 1, p = tid & 1;
        const __half* src = g_storeh + (size_t)par[2 * (m0 + row) + p] * D;
        BULK_G2S(smAu + (uint32_t)(row * AS + p * 256) * 2u, src, 512, mbarA);
    }
    if (tid == 0) { issueB(0); issueB(1); }

    float acc[2][4][4];
#pragma unroll
    for (int mt = 0; mt < 2; mt++)
#pragma unroll
        for (int nt = 0; nt < 4; nt++)
#pragma unroll
            for (int c = 0; c < 4; c++) acc[mt][nt][c] = 0.f;

    // one 32k sub-stage: warp tile 32x32, 8 LDS.128 + 16 HMMA
    // Bsub points at this warp's h-block for this sub ([128n][32k])
    auto do_sub = [&](const __half* Arow0, int astr, int koff, const __half* Bsub) {
        uint4 Av[2][2];
#pragma unroll
        for (int mt = 0; mt < 2; mt++) {
            const __half* ab = Arow0 + (warp_m * 32 + mt * 16 + g) * astr + koff + t4 * 8;
            Av[mt][0] = *(const uint4*)ab;
            Av[mt][1] = *(const uint4*)(ab + 8 * astr);
        }
        uint4 Bv[4];
#pragma unroll
        for (int nt = 0; nt < 4; nt++) {
            int cc = (warp_n & 3) * 32 + nt * 8 + g;
            Bv[nt] = *(const uint4*)(Bsub + cc * 32 + t4 * 8);
        }
#pragma unroll
        for (int step = 0; step < 2; step++) {
#pragma unroll
            for (int mt = 0; mt < 2; mt++) {
                uint32_t a0 = step ? Av[mt][0].z : Av[mt][0].x;
                uint32_t a1 = step ? Av[mt][1].z : Av[mt][1].x;
                uint32_t a2 = step ? Av[mt][0].w : Av[mt][0].y;
                uint32_t a3 = step ? Av[mt][1].w : Av[mt][1].y;
#pragma unroll
                for (int nt = 0; nt < 4; nt++) {
                    uint32_t b0 = step ? Bv[nt].z : Bv[nt].x;
                    uint32_t b1r = step ? Bv[nt].w : Bv[nt].y;
                    asm volatile(
                        "mma.sync.aligned.m16n8k16.row.col.f32.f16.f16.f32 "
                        "{%0,%1,%2,%3}, {%4,%5,%6,%7}, {%8,%9}, {%0,%1,%2,%3};"
                        : "+f"(acc[mt][nt][0]), "+f"(acc[mt][nt][1]),
                          "+f"(acc[mt][nt][2]), "+f"(acc[mt][nt][3])
                        : "r"(a0), "r"(a1), "r"(a2), "r"(a3), "r"(b0), "r"(b1r));
                }
            }
        }
    };

    const int hsel = (warp_n >> 2) * 16384;   // this warp's h-block within a slot

    // ================= GEMM1: superstages 0..NS1-1 =================
#pragma unroll
    for (int s = 0; s < NS1; s++) {
        if (s == 0) MBARRIER_WAIT_PARITY(mbarA, 0);
        MBARRIER_WAIT_PARITY(smem_to_u32(&mbars[s & 1]), (s >> 1) & 1);
        const __half* Bslot = smB + (s & 1) * SLOT + hsel;
#pragma unroll
        for (int sub = 0; sub < 4; sub++)
            do_sub(sm, AS, s * 128 + sub * 32, Bslot + sub * 4096);
        __syncthreads();                          // slot (s&1) readers done; A done at s=NS1-1
        if (tid == 0 && s + 2 < NSTG) issueB(s + 2);
    }

    // ---- H epilogue: bias1 + relu -> Hs (aliases A; safe after loop-tail sync) ----
    {
        const float* br = b1 + r * D;
#pragma unroll
        for (int mt = 0; mt < 2; mt++) {
            int rA = warp_m * 32 + mt * 16 + g;
#pragma unroll
            for (int nt = 0; nt < 4; nt++) {
                int col = warp_n * 32 + nt * 8 + 2 * t4;
                float bx = br[col], by = br[col + 1];
                float x0 = fmaxf(acc[mt][nt][0] + bx, 0.f);
                float y0 = fmaxf(acc[mt][nt][1] + by, 0.f);
                float x1 = fmaxf(acc[mt][nt][2] + bx, 0.f);
                float y1 = fmaxf(acc[mt][nt][3] + by, 0.f);
                int hoff = (col >> 5) * 32 + pos32(col & 31);
                *(__half2*)(Hs + rA * HS + hoff)       = __floats2half2_rn(x0, y0);
                *(__half2*)(Hs + (rA + 8) * HS + hoff) = __floats2half2_rn(x1, y1);
            }
        }
    }
    __syncthreads();                              // H visible to all warps

    // ================= GEMM2: superstages NS1..NSTG-1 (A = Hs) =================
#pragma unroll
    for (int mt = 0; mt < 2; mt++)
#pragma unroll
        for (int nt = 0; nt < 4; nt++)
#pragma unroll
            for (int c = 0; c < 4; c++) acc[mt][nt][c] = 0.f;

#pragma unroll
    for (int s2 = 0; s2 < NS2; s2++) {
        int gs = NS1 + s2;
        MBARRIER_WAIT_PARITY(smem_to_u32(&mbars[gs & 1]), (gs >> 1) & 1);
        const __half* Bslot = smB + (gs & 1) * SLOT + hsel;
#pragma unroll
        for (int sub = 0; sub < 4; sub++)
            do_sub(Hs, HS, s2 * 128 + sub * 32, Bslot + sub * 4096);
        // no further issues; no sync needed between GEMM2 stages
    }

    // ---- final epilogue: bias2 -> g_storeh interleaved ----
    {
        __half* Cbase = g_storeh + (size_t)(N0 + layer * NL) * D;
        const float* br = b2 + r * D;
#pragma unroll
        for (int mt = 0; mt < 2; mt++) {
            int mr0 = m0 + warp_m * 32 + mt * 16 + g;
#pragma unroll
            for (int nt = 0; nt < 4; nt++) {
                int col = warp_n * 32 + nt * 8 + 2 * t4;
                float bx = br[col], by = br[col + 1];
                float x0 = acc[mt][nt][0] + bx, y0 = acc[mt][nt][1] + by;
                float x1 = acc[mt][nt][2] + bx, y1 = acc[mt][nt][3] + by;
                int hoff = (col >> 5) * 32 + pos32(col & 31);
                *(__half2*)(Cbase + (size_t)mr0 * D + hoff)       = __floats2half2_rn(x0, y0);
                *(__half2*)(Cbase + (size_t)(mr0 + 8) * D + hoff) = __floats2half2_rn(x1, y1);
            }
        }
    }
}

// ---------------- eval + loss, last-block final reduction (deterministic) ----------------
__device__ __forceinline__ float softplusf(float x) {
    return fmaxf(x, 0.f) + log1pf(expf(-fabsf(x)));
}

__global__ void __launch_bounds__(256)
eval_partial(const float* __restrict__ pos_vals, const float* __restrict__ neg_vals,
             const float* __restrict__ eval_w, const float* __restrict__ eval_b,
             const float* __restrict__ pos_weight, float* __restrict__ out, int out_size) {
    __shared__ float red[8][5];
    __shared__ int is_last;
    const int lane = threadIdx.x & 31, warp = threadIdx.x >> 5;
    const int gw = blockIdx.x * 8 + warp;

    float w[8];
#pragma unroll
    for (int j = 0; j < 8; j++) {
        int q = lane * 8 + j;
        int k = (q >> 5) * 32 + invpos32(q & 31);
        w[j] = eval_w[k];
    }
    const float eb = *eval_b;
    const float pw = *pos_weight;

    float loss = 0.f, posOK = 0.f, negOK = 0.f, posTot = 0.f, negTot = 0.f;

    for (int node = gw; node < TOTAL; node += EVAL_BLOCKS * 8) {
        const __half2* row = (const __half2*)(g_storeh + (size_t)node * D);
        float s = 0.f;
#pragma unroll
        for (int i = 0; i < 4; i++) {
            float2 v = __half22float2(row[lane * 4 + i]);
            s += v.x * w[2 * i] + v.y * w[2 * i + 1];
        }
#pragma unroll
        for (int off = 16; off; off >>= 1) s += __shfl_xor_sync(0xffffffffu, s, off);
        if (lane == 0) {
            float x = s + eb;
            float pv = pos_vals[node], nv = neg_vals[node];
            float tot = pv + nv;
            if (tot > 0.f) {
                float tgt = pv / fmaxf(tot, 1e-9f);
                float bce = pw * tgt * softplusf(-x) + (1.f - tgt) * softplusf(x);
                loss += tot * bce;
                posTot += pv; negTot += nv;
                if (x >= 0.f) posOK += pv; else negOK += nv;
            }
        }
    }
    if (lane == 0) {
        red[warp][0] = loss; red[warp][1] = posOK; red[warp][2] = negOK;
        red[warp][3] = posTot; red[warp][4] = negTot;
    }
    __syncthreads();
    if (threadIdx.x < 5) {
        float t = 0.f;
        for (int i = 0; i < 8; i++) t += red[i][threadIdx.x];
        g_partials[blockIdx.x * 5 + threadIdx.x] = t;
    }
    __threadfence();
    __syncthreads();
    if (threadIdx.x == 0)
        is_last = (atomicAdd(&g_evalcnt, 1) == EVAL_BLOCKS - 1) ? 1 : 0;
    __syncthreads();
    if (is_last && threadIdx.x < 32) {
        __threadfence();
        float s[5] = {0.f, 0.f, 0.f, 0.f, 0.f};
        for (int i = threadIdx.x; i < EVAL_BLOCKS; i += 32) {
            const volatile float* p = g_partials + i * 5;
#pragma unroll
            for (int c = 0; c < 5; c++) s[c] += p[c];
        }
#pragma unroll
        for (int c = 0; c < 5; c++)
#pragma unroll
            for (int off = 16; off; off >>= 1)
                s[c] += __shfl_xor_sync(0xffffffffu, s[c], off);
        if (threadIdx.x == 0) {
            float pos_rate = (s[3] > 0.f) ? s[1] / fmaxf(s[3], 1e-9f) : 1.f;
            float neg_rate = (s[4] > 0.f) ? s[2] / fmaxf(s[4], 1e-9f) : 1.f;
            if (out_size >= 1) out[0] = s[0];
            if (out_size >= 2) out[1] = pos_rate;
            if (out_size >= 3) out[2] = neg_rate;
            g_evalcnt = 0;                      // self-clean for next graph replay
        }
    }
}

// ---------------- launch ----------------
extern "C" void kernel_launch(void* const* d_in, const int* in_sizes, int n_in,
                              void* d_out, int out_size) {
    const int*   thax       = (const int*)  d_in[0];
    const int*   par_idx    = (const int*)  d_in[1];
    const float* pos_vals   = (const float*)d_in[2];
    const float* neg_vals   = (const float*)d_in[3];
    const float* init_table = (const float*)d_in[4];
    const float* W1         = (const float*)d_in[5];
    const float* b1         = (const float*)d_in[6];
    const float* W2         = (const float*)d_in[7];
    const float* b2         = (const float*)d_in[8];
    const float* eval_w     = (const float*)d_in[9];
    const float* eval_b     = (const float*)d_in[10];
    const float* pos_weight = (const float*)d_in[11];
    float* out = (float*)d_out;

    cudaFuncSetAttribute(layer_fused,
                         cudaFuncAttributeMaxDynamicSharedMemorySize, SMEM_BYTES);

    prologue<<<2048 + 256 + 128, 256>>>(thax, init_table, W1, W2);

    for (int l = 0; l < L; l++) {
        layer_fused<<<NL / 64, 512, SMEM_BYTES>>>(
            b1, b2, par_idx + (size_t)l * NL * 2, l);
    }

    eval_partial<<<EVAL_BLOCKS, 256>>>(pos_vals, neg_vals, eval_w, eval_b,
                                       pos_weight, out, out_size);
}